// round 5
// baseline (speedup 1.0000x reference)
#include <cuda_runtime.h>
#include <math.h>

// Problem constants (fixed shapes: z_i, z_j are [4096, 128] fp32)
#define D      128
#define BHALF  4096
#define NROWS  8192
#define TILE   128
#define NT     (NROWS / TILE)          // 64 tiles per dim
#define NPAIRS (NT * (NT + 1) / 2)     // 2080 triangular tile pairs
#define KC     32                      // K staging chunk

// Scratch (no device allocation allowed -> __device__ globals)
__device__ float g_zn[NROWS * D];   // normalized rows, fp32 (4 MB, L2-resident)
__device__ float g_S[NROWS];        // per-row sum of exp(sim) excluding diag
__device__ float g_pos[NROWS];      // per-row positive logit

// ---------------------------------------------------------------------------
// Kernel 1: row L2-normalize (with 1e-8 clamp, matching torch CosineSimilarity
// semantics in the reference) + zero the row-sum accumulator for this replay.
// One block (128 threads) per row.
// ---------------------------------------------------------------------------
__global__ void k_normalize(const float* __restrict__ zi,
                            const float* __restrict__ zj) {
    const int row = blockIdx.x;
    const int t   = threadIdx.x;           // 0..127
    const float* src = (row < BHALF) ? (zi + (size_t)row * D)
                                     : (zj + (size_t)(row - BHALF) * D);
    float v  = src[t];
    float ss = v * v;
    #pragma unroll
    for (int o = 16; o > 0; o >>= 1)
        ss += __shfl_down_sync(0xffffffffu, ss, o);

    __shared__ float ws[4];
    if ((t & 31) == 0) ws[t >> 5] = ss;
    __syncthreads();
    float tot  = ws[0] + ws[1] + ws[2] + ws[3];
    float norm = fmaxf(sqrtf(tot), 1e-8f);

    g_zn[(size_t)row * D + t] = v / norm;
    if (t == 0) g_S[row] = 0.0f;           // re-zero every launch (graph replay safe)
}

// ---------------------------------------------------------------------------
// Kernel 2: triangular tiled sim computation.
// Each block handles one 128x128 tile (ti, tj) with tj >= ti.
//   - 256 threads, each computes an 8x8 fp32 register micro-tile.
//   - Off-diagonal tiles contribute exp() to BOTH row sums (I side, via
//     half-warp shuffle reduce + 1 atomic/row) and column sums (J side, via
//     per-thread global atomics). Diagonal tiles contribute rows only and
//     mask the self element.
//   - Positives: gj - gi == BHALF happens exactly in tiles (a, a+32); the
//     symmetric value serves both pos[gi] and pos[gj].
// ---------------------------------------------------------------------------
__global__ __launch_bounds__(256)
void k_sim() {
    // Decode linear block id -> triangular (ti, tj), tj >= ti.
    int ti = 0, tj;
    {
        int rem = blockIdx.x;
        int rowlen = NT;
        while (rem >= rowlen) { rem -= rowlen; rowlen--; ti++; }
        tj = ti + rem;
    }
    const int I0 = ti * TILE;
    const int J0 = tj * TILE;
    const bool diag = (ti == tj);

    __shared__ float As[TILE][KC + 1];   // +1 pad: conflict-free strided reads
    __shared__ float Bs[TILE][KC + 1];

    const int tid = threadIdx.x;         // 0..255
    const int tx  = tid & 15;            // column group (8 cols each)
    const int ty  = tid >> 4;            // row group (8 rows each)

    float acc[8][8];
    #pragma unroll
    for (int r = 0; r < 8; r++)
        #pragma unroll
        for (int c = 0; c < 8; c++) acc[r][c] = 0.0f;

    for (int kk = 0; kk < D; kk += KC) {
        __syncthreads();
        // Stage A and B K-chunks: 128 rows x 32 k each; 256 threads x 16 elems.
        // Per-warp global reads are 128B-contiguous (one row, 32 floats).
        #pragma unroll
        for (int it = 0; it < 16; it++) {
            int e = tid + 256 * it;      // 0..4095
            int r = e >> 5;
            int c = e & 31;
            As[r][c] = g_zn[(size_t)(I0 + r) * D + kk + c];
        }
        #pragma unroll
        for (int it = 0; it < 16; it++) {
            int e = tid + 256 * it;
            int r = e >> 5;
            int c = e & 31;
            Bs[r][c] = g_zn[(size_t)(J0 + r) * D + kk + c];
        }
        __syncthreads();

        #pragma unroll 8
        for (int k = 0; k < KC; k++) {
            float a[8], b[8];
            #pragma unroll
            for (int r = 0; r < 8; r++) a[r] = As[ty * 8 + r][k];
            #pragma unroll
            for (int c = 0; c < 8; c++) b[c] = Bs[tx * 8 + c][k];
            #pragma unroll
            for (int r = 0; r < 8; r++)
                #pragma unroll
                for (int c = 0; c < 8; c++)
                    acc[r][c] = fmaf(a[r], b[c], acc[r][c]);
        }
    }

    // Epilogue: sim = 2 * cos (temperature 0.5). Range [-2, 2] -> exp is safe
    // without a max-subtraction pass.
    float colsum[8];
    #pragma unroll
    for (int c = 0; c < 8; c++) colsum[c] = 0.0f;

    #pragma unroll
    for (int r = 0; r < 8; r++) {
        const int gi = I0 + ty * 8 + r;
        float rowsum = 0.0f;
        #pragma unroll
        for (int c = 0; c < 8; c++) {
            const int gj = J0 + tx * 8 + c;
            float s = 2.0f * acc[r][c];
            float e = __expf(s);
            if (gi == gj) e = 0.0f;          // self-similarity masked (diag tile)
            rowsum += e;
            if (!diag) colsum[c] += e;       // transpose contribution
            if (gj - gi == BHALF) {          // positive pair (and its mirror)
                g_pos[gi] = s;
                g_pos[gj] = s;
            }
        }
        // Reduce rowsum across the 16 tx-threads (contiguous half-warp).
        #pragma unroll
        for (int o = 8; o > 0; o >>= 1)
            rowsum += __shfl_down_sync(0xffffffffu, rowsum, o, 16);
        if (tx == 0) atomicAdd(&g_S[gi], rowsum);
    }

    if (!diag) {
        #pragma unroll
        for (int c = 0; c < 8; c++) {
            const int gj = J0 + tx * 8 + c;
            atomicAdd(&g_S[gj], colsum[c]);
        }
    }
}

// ---------------------------------------------------------------------------
// Kernel 3: loss = mean(log(S_i) - pos_i)
// ---------------------------------------------------------------------------
__global__ void k_final(float* __restrict__ out) {
    const int t = threadIdx.x;   // 256 threads, 1 block
    float acc = 0.0f;
    for (int i = t; i < NROWS; i += 256)
        acc += logf(g_S[i]) - g_pos[i];

    #pragma unroll
    for (int o = 16; o > 0; o >>= 1)
        acc += __shfl_down_sync(0xffffffffu, acc, o);

    __shared__ float ws[8];
    if ((t & 31) == 0) ws[t >> 5] = acc;
    __syncthreads();
    if (t == 0) {
        float tot = 0.0f;
        #pragma unroll
        for (int w = 0; w < 8; w++) tot += ws[w];
        out[0] = tot * (1.0f / (float)NROWS);
    }
}

// ---------------------------------------------------------------------------
extern "C" void kernel_launch(void* const* d_in, const int* in_sizes, int n_in,
                              void* d_out, int out_size) {
    (void)in_sizes; (void)n_in; (void)out_size;
    const float* zi = (const float*)d_in[0];
    const float* zj = (const float*)d_in[1];
    float* out = (float*)d_out;

    k_normalize<<<NROWS, D>>>(zi, zj);
    k_sim<<<NPAIRS, 256>>>();
    k_final<<<1, 256>>>(out);
}

// round 8
// speedup vs baseline: 2.5698x; 2.5698x over previous
#include <cuda_runtime.h>
#include <cuda_bf16.h>
#include <math.h>
#include <cstdint>

// Fixed shapes: z_i, z_j are [4096, 128] fp32
#define D       128
#define BHALF   4096
#define NROWS   8192
#define NT      64
#define NTILES  (NT * NT)            // 4096 tiles of 128x128 (row-sums only)

// Scratch (__device__ globals; no allocation allowed)
__device__ __nv_bfloat16 g_zbf[NROWS * D];  // normalized rows, bf16 (2 MB, L2)
__device__ float g_S[NROWS];                // per-row sum of exp(sim), self excluded
__device__ float g_pos[NROWS];              // per-row positive logit

// ---------------------------------------------------------------------------
__device__ __forceinline__ uint32_t smem_u32(const void* p) {
    uint32_t a;
    asm("{ .reg .u64 t; cvta.to.shared.u64 t, %1; cvt.u32.u64 %0, t; }"
        : "=r"(a) : "l"(p));
    return a;
}
__device__ __forceinline__ void ldmatrix_x4(uint32_t* r, uint32_t a) {
    asm volatile("ldmatrix.sync.aligned.m8n8.x4.shared.b16 {%0,%1,%2,%3}, [%4];"
                 : "=r"(r[0]), "=r"(r[1]), "=r"(r[2]), "=r"(r[3]) : "r"(a));
}
__device__ __forceinline__ void ldmatrix_x2(uint32_t* r, uint32_t a) {
    asm volatile("ldmatrix.sync.aligned.m8n8.x2.shared.b16 {%0,%1}, [%2];"
                 : "=r"(r[0]), "=r"(r[1]) : "r"(a));
}
// D[16x8] += A[16x16] * B[16x8] (A row-major frag, B col-major frag), bf16->fp32
__device__ __forceinline__ void mma_bf16(float* c, const uint32_t* a,
                                         const uint32_t* b) {
    asm volatile(
        "mma.sync.aligned.m16n8k16.row.col.f32.bf16.bf16.f32 "
        "{%0,%1,%2,%3}, {%4,%5,%6,%7}, {%8,%9}, {%0,%1,%2,%3};"
        : "+f"(c[0]), "+f"(c[1]), "+f"(c[2]), "+f"(c[3])
        : "r"(a[0]), "r"(a[1]), "r"(a[2]), "r"(a[3]), "r"(b[0]), "r"(b[1]));
}

// ---------------------------------------------------------------------------
// Kernel 1: row L2-normalize (1e-8 clamp) -> bf16, zero g_S. One warp per row.
// ---------------------------------------------------------------------------
__global__ __launch_bounds__(256)
void k_normalize(const float* __restrict__ zi, const float* __restrict__ zj) {
    const int row  = (blockIdx.x << 3) + (threadIdx.x >> 5);
    const int lane = threadIdx.x & 31;
    const float* src = (row < BHALF) ? (zi + (size_t)row * D)
                                     : (zj + (size_t)(row - BHALF) * D);
    float4 v = reinterpret_cast<const float4*>(src)[lane];
    float ss = v.x * v.x + v.y * v.y + v.z * v.z + v.w * v.w;
    #pragma unroll
    for (int o = 16; o > 0; o >>= 1) ss += __shfl_xor_sync(0xffffffffu, ss, o);
    float inv = 1.0f / fmaxf(sqrtf(ss), 1e-8f);

    __nv_bfloat162* dst = reinterpret_cast<__nv_bfloat162*>(g_zbf + (size_t)row * D);
    dst[2 * lane + 0] = __floats2bfloat162_rn(v.x * inv, v.y * inv);
    dst[2 * lane + 1] = __floats2bfloat162_rn(v.z * inv, v.w * inv);
    if (lane == 0) g_S[row] = 0.0f;
}

// ---------------------------------------------------------------------------
// Kernel 2: one 128x128 tile per CTA via mma.sync (HMMA), register accumulators.
// 8 warps: warp (wr in 0..1, wc in 0..3) owns a 64x32 sub-tile = 4x4 frags of
// m16n8. K=128 staged in two 64-wide halves (16 KB A + 16 KB B static smem),
// XOR-swizzled rows so uint4 stores and ldmatrix reads are conflict-free.
// Epilogue in registers: exp(2*cos), diag mask, positive capture, quad-shuffle
// row reduce, one atomicAdd per row fragment.
// ---------------------------------------------------------------------------
__global__ __launch_bounds__(256)
void k_sim() {
    __shared__ __align__(16) uint8_t sA[128 * 128];   // 128 rows x 64 bf16
    __shared__ __align__(16) uint8_t sB[128 * 128];

    const int tid  = threadIdx.x;
    const int wid  = tid >> 5;
    const int lane = tid & 31;
    const int ti = blockIdx.x >> 6, tj = blockIdx.x & (NT - 1);
    const int I0 = ti * 128, J0 = tj * 128;
    const int wr = wid >> 2;          // 0..1 : 64-row block
    const int wc = wid & 3;           // 0..3 : 32-col block
    const uint32_t sa = smem_u32(sA), sb = smem_u32(sB);

    // ldmatrix per-thread row/subchunk assignment
    // A x4 groups g=lane/8: g&1 -> +8 rows, g>>1 -> k-subchunk (16B) select
    const int a_row = wr * 64 + ((lane >> 3) & 1) * 8 + (lane & 7);
    const int a_cb  = lane >> 4;                 // 0/1
    const int b_row = wc * 32 + (lane & 7);      // +ni*8 later
    const int b_cb  = (lane >> 3) & 1;           // x2 uses threads 0..15
    const int a_swz = a_row & 7;
    const int b_swz = b_row & 7;

    float acc[4][4][4];
    #pragma unroll
    for (int mi = 0; mi < 4; mi++)
        #pragma unroll
        for (int ni = 0; ni < 4; ni++)
            #pragma unroll
            for (int f = 0; f < 4; f++) acc[mi][ni][f] = 0.0f;

    #pragma unroll
    for (int s = 0; s < 2; s++) {                 // K halves: k base = s*64
        __syncthreads();
        // Stage: 1024 16B-chunks for each of A,B; 4 per thread per matrix.
        #pragma unroll
        for (int i = 0; i < 4; i++) {
            const int e = tid + 256 * i;          // 0..1023
            const int r = e >> 3, c = e & 7;      // row, 16B chunk (8 per row)
            const uint32_t off = (uint32_t)r * 128u + (uint32_t)((c ^ (r & 7)) << 4);
            *reinterpret_cast<uint4*>(sA + off) =
                *reinterpret_cast<const uint4*>(g_zbf + (size_t)(I0 + r) * D + s * 64 + c * 8);
            *reinterpret_cast<uint4*>(sB + off) =
                *reinterpret_cast<const uint4*>(g_zbf + (size_t)(J0 + r) * D + s * 64 + c * 8);
        }
        __syncthreads();

        #pragma unroll
        for (int kc = 0; kc < 4; kc++) {          // 16-wide k chunks
            uint32_t af[4][4], bf[4][2];
            #pragma unroll
            for (int mi = 0; mi < 4; mi++) {
                const uint32_t addr = sa + (uint32_t)(a_row + mi * 16) * 128u
                    + (uint32_t)(((kc * 2 + a_cb) ^ a_swz) << 4);
                ldmatrix_x4(af[mi], addr);
            }
            #pragma unroll
            for (int ni = 0; ni < 4; ni++) {
                const uint32_t addr = sb + (uint32_t)(b_row + ni * 8) * 128u
                    + (uint32_t)(((kc * 2 + b_cb) ^ b_swz) << 4);
                ldmatrix_x2(bf[ni], addr);
            }
            #pragma unroll
            for (int mi = 0; mi < 4; mi++)
                #pragma unroll
                for (int ni = 0; ni < 4; ni++)
                    mma_bf16(acc[mi][ni], af[mi], bf[ni]);
        }
    }

    // Epilogue. c-frag mapping: c0:(m=trow, n=tcol2) c1:(trow, tcol2+1)
    //                           c2:(trow+8, tcol2)   c3:(trow+8, tcol2+1)
    const int  trow  = lane >> 2;
    const int  tcol2 = (lane & 3) * 2;
    const bool diag  = (ti == tj);

    #pragma unroll
    for (int mi = 0; mi < 4; mi++) {
        const int gi0 = I0 + wr * 64 + mi * 16 + trow;
        const int gi1 = gi0 + 8;
        const int p0 = gi0 ^ BHALF, p1 = gi1 ^ BHALF;  // positive columns
        float rs0 = 0.0f, rs1 = 0.0f;
        #pragma unroll
        for (int ni = 0; ni < 4; ni++) {
            const int gj = J0 + wc * 32 + ni * 8 + tcol2;
            const float* c = acc[mi][ni];
            float s0 = c[0] + c[0], s1 = c[1] + c[1];   // sim = cos / 0.5
            float s2 = c[2] + c[2], s3 = c[3] + c[3];
            float e0 = __expf(s0), e1 = __expf(s1);
            float e2 = __expf(s2), e3 = __expf(s3);
            if (diag) {                                  // mask self-similarity
                if (gj     == gi0) e0 = 0.0f;
                if (gj + 1 == gi0) e1 = 0.0f;
                if (gj     == gi1) e2 = 0.0f;
                if (gj + 1 == gi1) e3 = 0.0f;
            }
            if (gj     == p0) g_pos[gi0] = s0;
            if (gj + 1 == p0) g_pos[gi0] = s1;
            if (gj     == p1) g_pos[gi1] = s2;
            if (gj + 1 == p1) g_pos[gi1] = s3;
            rs0 += e0 + e1;
            rs1 += e2 + e3;
        }
        // Reduce over the 4 column-lanes (lane&3) of this row.
        rs0 += __shfl_xor_sync(0xffffffffu, rs0, 1);
        rs0 += __shfl_xor_sync(0xffffffffu, rs0, 2);
        rs1 += __shfl_xor_sync(0xffffffffu, rs1, 1);
        rs1 += __shfl_xor_sync(0xffffffffu, rs1, 2);
        if ((lane & 3) == 0) {
            atomicAdd(&g_S[gi0], rs0);
            atomicAdd(&g_S[gi1], rs1);
        }
    }
}

// ---------------------------------------------------------------------------
// Kernel 3: loss = mean(log(S_i) - pos_i)
// ---------------------------------------------------------------------------
__global__ void k_final(float* __restrict__ out) {
    const int t = threadIdx.x;   // 256 threads, 1 block
    float acc = 0.0f;
    for (int i = t; i < NROWS; i += 256)
        acc += logf(g_S[i]) - g_pos[i];
    #pragma unroll
    for (int o = 16; o > 0; o >>= 1)
        acc += __shfl_down_sync(0xffffffffu, acc, o);
    __shared__ float ws[8];
    if ((t & 31) == 0) ws[t >> 5] = acc;
    __syncthreads();
    if (t == 0) {
        float tot = 0.0f;
        #pragma unroll
        for (int w = 0; w < 8; w++) tot += ws[w];
        out[0] = tot * (1.0f / (float)NROWS);
    }
}

// ---------------------------------------------------------------------------
extern "C" void kernel_launch(void* const* d_in, const int* in_sizes, int n_in,
                              void* d_out, int out_size) {
    (void)in_sizes; (void)n_in; (void)out_size;
    const float* zi = (const float*)d_in[0];
    const float* zj = (const float*)d_in[1];
    float* out = (float*)d_out;

    k_normalize<<<NROWS / 8, 256>>>(zi, zj);
    k_sim<<<NTILES, 256>>>();
    k_final<<<1, 256>>>(out);
}

// round 12
// speedup vs baseline: 6.6345x; 2.5817x over previous
#include <cuda_runtime.h>
#include <cuda_bf16.h>
#include <math.h>
#include <cstdint>

// Fixed shapes: z_i, z_j are [4096, 128] fp32
#define D       128
#define BHALF   4096
#define NROWS   8192
#define NT      64
#define NPAIRS  (NT * (NT + 1) / 2)   // 2080 triangular 128x128 tiles

// Scratch (__device__ globals; no allocation allowed)
__device__ __nv_bfloat16 g_zbf[NROWS * D];  // normalized rows, bf16 (2 MB, L2)
__device__ float g_S[NROWS];                // per-row sum of exp(sim), self excluded
__device__ float g_pos[NROWS];              // per-row positive logit

// ---------------------------------------------------------------------------
__device__ __forceinline__ uint32_t smem_u32(const void* p) {
    uint32_t a;
    asm("{ .reg .u64 t; cvta.to.shared.u64 t, %1; cvt.u32.u64 %0, t; }"
        : "=r"(a) : "l"(p));
    return a;
}
__device__ __forceinline__ void ldmatrix_x4(uint32_t* r, uint32_t a) {
    asm volatile("ldmatrix.sync.aligned.m8n8.x4.shared.b16 {%0,%1,%2,%3}, [%4];"
                 : "=r"(r[0]), "=r"(r[1]), "=r"(r[2]), "=r"(r[3]) : "r"(a));
}
__device__ __forceinline__ void ldmatrix_x2(uint32_t* r, uint32_t a) {
    asm volatile("ldmatrix.sync.aligned.m8n8.x2.shared.b16 {%0,%1}, [%2];"
                 : "=r"(r[0]), "=r"(r[1]) : "r"(a));
}
__device__ __forceinline__ void mma_bf16(float* c, const uint32_t* a,
                                         const uint32_t* b) {
    asm volatile(
        "mma.sync.aligned.m16n8k16.row.col.f32.bf16.bf16.f32 "
        "{%0,%1,%2,%3}, {%4,%5,%6,%7}, {%8,%9}, {%0,%1,%2,%3};"
        : "+f"(c[0]), "+f"(c[1]), "+f"(c[2]), "+f"(c[3])
        : "r"(a[0]), "r"(a[1]), "r"(a[2]), "r"(a[3]), "r"(b[0]), "r"(b[1]));
}
#define CP_ASYNC16(dst, src) \
    asm volatile("cp.async.cg.shared.global [%0], [%1], 16;" \
                 :: "r"(dst), "l"(src) : "memory")
#define CP_COMMIT() asm volatile("cp.async.commit_group;" ::: "memory")
#define CP_WAIT0()  asm volatile("cp.async.wait_group 0;" ::: "memory")

// ---------------------------------------------------------------------------
// Kernel 1: row L2-normalize (1e-8 clamp) -> bf16, zero g_S (+ d_out).
// One warp per row.
// ---------------------------------------------------------------------------
__global__ __launch_bounds__(256)
void k_normalize(const float* __restrict__ zi, const float* __restrict__ zj,
                 float* __restrict__ out) {
    const int row  = (blockIdx.x << 3) + (threadIdx.x >> 5);
    const int lane = threadIdx.x & 31;
    const float* src = (row < BHALF) ? (zi + (size_t)row * D)
                                     : (zj + (size_t)(row - BHALF) * D);
    float4 v = reinterpret_cast<const float4*>(src)[lane];
    float ss = v.x * v.x + v.y * v.y + v.z * v.z + v.w * v.w;
    #pragma unroll
    for (int o = 16; o > 0; o >>= 1) ss += __shfl_xor_sync(0xffffffffu, ss, o);
    float inv = 1.0f / fmaxf(sqrtf(ss), 1e-8f);

    __nv_bfloat162* dst = reinterpret_cast<__nv_bfloat162*>(g_zbf + (size_t)row * D);
    dst[2 * lane + 0] = __floats2bfloat162_rn(v.x * inv, v.y * inv);
    dst[2 * lane + 1] = __floats2bfloat162_rn(v.z * inv, v.w * inv);
    if (lane == 0) g_S[row] = 0.0f;
    if (row == 0 && lane == 0) out[0] = 0.0f;   // re-zero every replay
}

// ---------------------------------------------------------------------------
// Kernel 2: triangular (tj >= ti) 128x128 tiles via mma.sync (HMMA).
// 8 warps; warp (wr,wc) owns a 64x32 sub-tile = 4x4 m16n8 fragments.
// Full K=128 staged in one shot via cp.async into two 128x128B half-buffers
// per matrix (64 KB dynamic smem), XOR-swizzled for conflict-free ldmatrix.
// Epilogue: exp(2*cos); row sums (quad shuffle + atomic) always; column sums
// (stride-4/8/16 xor shuffle + atomic) for off-diagonal tiles (transpose
// contribution). Positives write g_pos for both the row and its mirror.
// ---------------------------------------------------------------------------
__global__ __launch_bounds__(256, 2)
void k_sim() {
    extern __shared__ __align__(16) uint8_t smem[];
    uint8_t* sA = smem;              // 2 halves x (128 rows x 128 B)
    uint8_t* sB = smem + 32768;

    const int tid  = threadIdx.x;
    const int wid  = tid >> 5;
    const int lane = tid & 31;

    // Triangular decode
    int ti = 0, tj;
    {
        int rem = blockIdx.x, rowlen = NT;
        while (rem >= rowlen) { rem -= rowlen; rowlen--; ti++; }
        tj = ti + rem;
    }
    const int I0 = ti * 128, J0 = tj * 128;
    const bool diag = (ti == tj);

    const int wr = wid >> 2;          // 0..1 : 64-row block
    const int wc = wid & 3;           // 0..3 : 32-col block
    const uint32_t sa = smem_u32(sA), sb = smem_u32(sB);

    const int a_row = wr * 64 + ((lane >> 3) & 1) * 8 + (lane & 7);
    const int a_cb  = lane >> 4;                 // 0/1 (16B k-subchunk)
    const int b_row = wc * 32 + (lane & 7);
    const int b_cb  = (lane >> 3) & 1;
    const int a_swz = a_row & 7;
    const int b_swz = b_row & 7;

    // ---- Stage full K=128 for A and B with cp.async ----
    #pragma unroll
    for (int i = 0; i < 8; i++) {
        const int e = tid + 256 * i;             // 0..2047
        const int r = e >> 4, c16 = e & 15;      // row, 16B chunk over full K
        const int half = c16 >> 3, c = c16 & 7;
        const uint32_t off = (uint32_t)half * 16384u + (uint32_t)r * 128u
                           + (uint32_t)((c ^ (r & 7)) << 4);
        CP_ASYNC16(sa + off,
                   (const void*)(g_zbf + (size_t)(I0 + r) * D + c16 * 8));
        CP_ASYNC16(sb + off,
                   (const void*)(g_zbf + (size_t)(J0 + r) * D + c16 * 8));
    }
    CP_COMMIT();

    float acc[4][4][4];
    #pragma unroll
    for (int mi = 0; mi < 4; mi++)
        #pragma unroll
        for (int ni = 0; ni < 4; ni++)
            #pragma unroll
            for (int f = 0; f < 4; f++) acc[mi][ni][f] = 0.0f;

    CP_WAIT0();
    __syncthreads();

    // ---- Main loop: 8 chunks of k=16 ----
    #pragma unroll
    for (int kk = 0; kk < 8; kk++) {
        const uint32_t hbase = (uint32_t)(kk >> 2) * 16384u;
        const int kc = kk & 3;
        uint32_t af[4][4], bf[4][2];
        #pragma unroll
        for (int mi = 0; mi < 4; mi++) {
            const uint32_t addr = sa + hbase + (uint32_t)(a_row + mi * 16) * 128u
                + (uint32_t)(((kc * 2 + a_cb) ^ a_swz) << 4);
            ldmatrix_x4(af[mi], addr);
        }
        #pragma unroll
        for (int ni = 0; ni < 4; ni++) {
            const uint32_t addr = sb + hbase + (uint32_t)(b_row + ni * 8) * 128u
                + (uint32_t)(((kc * 2 + b_cb) ^ b_swz) << 4);
            ldmatrix_x2(bf[ni], addr);
        }
        #pragma unroll
        for (int mi = 0; mi < 4; mi++)
            #pragma unroll
            for (int ni = 0; ni < 4; ni++)
                mma_bf16(acc[mi][ni], af[mi], bf[ni]);
    }

    // ---- Epilogue ----
    // c-frag: c0:(trow, tcol2) c1:(trow, tcol2+1) c2:(trow+8, .) c3:(trow+8, .+1)
    const int trow  = lane >> 2;
    const int tcol2 = (lane & 3) * 2;

    float cs[4][2];                   // column sums over this thread's 8 rows
    #pragma unroll
    for (int ni = 0; ni < 4; ni++) { cs[ni][0] = 0.0f; cs[ni][1] = 0.0f; }

    #pragma unroll
    for (int mi = 0; mi < 4; mi++) {
        const int gi0 = I0 + wr * 64 + mi * 16 + trow;
        const int gi1 = gi0 + 8;
        const int p0 = gi0 ^ BHALF, p1 = gi1 ^ BHALF;
        float rs0 = 0.0f, rs1 = 0.0f;
        #pragma unroll
        for (int ni = 0; ni < 4; ni++) {
            const int gj = J0 + wc * 32 + ni * 8 + tcol2;
            const float* c = acc[mi][ni];
            float s0 = c[0] + c[0], s1 = c[1] + c[1];   // sim = cos / 0.5
            float s2 = c[2] + c[2], s3 = c[3] + c[3];
            float e0 = __expf(s0), e1 = __expf(s1);
            float e2 = __expf(s2), e3 = __expf(s3);
            if (diag) {                                  // mask self-similarity
                if (gj     == gi0) e0 = 0.0f;
                if (gj + 1 == gi0) e1 = 0.0f;
                if (gj     == gi1) e2 = 0.0f;
                if (gj + 1 == gi1) e3 = 0.0f;
            }
            if (gj     == p0) { g_pos[gi0] = s0; g_pos[gj]     = s0; }
            if (gj + 1 == p0) { g_pos[gi0] = s1; g_pos[gj + 1] = s1; }
            if (gj     == p1) { g_pos[gi1] = s2; g_pos[gj]     = s2; }
            if (gj + 1 == p1) { g_pos[gi1] = s3; g_pos[gj + 1] = s3; }
            rs0 += e0 + e1;
            rs1 += e2 + e3;
            cs[ni][0] += e0 + e2;     // transpose (column) contribution
            cs[ni][1] += e1 + e3;
        }
        rs0 += __shfl_xor_sync(0xffffffffu, rs0, 1);
        rs0 += __shfl_xor_sync(0xffffffffu, rs0, 2);
        rs1 += __shfl_xor_sync(0xffffffffu, rs1, 1);
        rs1 += __shfl_xor_sync(0xffffffffu, rs1, 2);
        if ((lane & 3) == 0) {
            atomicAdd(&g_S[gi0], rs0);
            atomicAdd(&g_S[gi1], rs1);
        }
    }

    if (!diag) {
        #pragma unroll
        for (int ni = 0; ni < 4; ni++) {
            float c0 = cs[ni][0], c1 = cs[ni][1];
            #pragma unroll
            for (int o = 4; o < 32; o <<= 1) {
                c0 += __shfl_xor_sync(0xffffffffu, c0, o);
                c1 += __shfl_xor_sync(0xffffffffu, c1, o);
            }
            if (lane < 4) {
                const int gj = J0 + wc * 32 + ni * 8 + lane * 2;
                atomicAdd(&g_S[gj],     c0);
                atomicAdd(&g_S[gj + 1], c1);
            }
        }
    }
}

// ---------------------------------------------------------------------------
// Kernel 3: loss = mean(log(S_i) - pos_i), 32 blocks + atomic accumulate.
// ---------------------------------------------------------------------------
__global__ __launch_bounds__(256)
void k_final(float* __restrict__ out) {
    const int i = blockIdx.x * 256 + threadIdx.x;   // exactly 8192 threads
    float acc = logf(g_S[i]) - g_pos[i];
    #pragma unroll
    for (int o = 16; o > 0; o >>= 1)
        acc += __shfl_down_sync(0xffffffffu, acc, o);
    __shared__ float ws[8];
    if ((threadIdx.x & 31) == 0) ws[threadIdx.x >> 5] = acc;
    __syncthreads();
    if (threadIdx.x == 0) {
        float tot = 0.0f;
        #pragma unroll
        for (int w = 0; w < 8; w++) tot += ws[w];
        atomicAdd(out, tot * (1.0f / (float)NROWS));
    }
}

// ---------------------------------------------------------------------------
extern "C" void kernel_launch(void* const* d_in, const int* in_sizes, int n_in,
                              void* d_out, int out_size) {
    (void)in_sizes; (void)n_in; (void)out_size;
    const float* zi = (const float*)d_in[0];
    const float* zj = (const float*)d_in[1];
    float* out = (float*)d_out;

    cudaFuncSetAttribute(k_sim, cudaFuncAttributeMaxDynamicSharedMemorySize, 65536);

    k_normalize<<<NROWS / 8, 256>>>(zi, zj, out);
    k_sim<<<NPAIRS, 256, 65536>>>();
    k_final<<<NROWS / 256, 256>>>(out);
}